// round 8
// baseline (speedup 1.0000x reference)
#include <cuda_runtime.h>
#include <cuda_bf16.h>
#include <math.h>
#include <stdint.h>

// ---------------------------------------------------------------------------
// Problem constants
// ---------------------------------------------------------------------------
#define LNUM 4
#define DDIM 1024
#define HNUM 16
#define HD   64
#define MDIM 4096
#define SLEN 1024
#define BNUM 2
#define NTOK (BNUM*SLEN)        // 2048
#define D3   (3*DDIM)           // 3072
#define EPS  1e-5f

// Weight split array layout (element offsets)
#define W_IN1_OFF   0u
#define W_OUT1_OFF  12582912u
#define W_IN2_OFF   16777216u
#define W_OUT2_OFF  29360128u
#define FW1_OFF     33554432u
#define FW2_OFF     50331648u
#define WTOTAL      67108864u

// ---------------------------------------------------------------------------
// Device scratch (no allocations allowed)
// ---------------------------------------------------------------------------
static __device__ float g_proj[NTOK*DDIM];
static __device__ float g_x   [NTOK*DDIM];
static __device__ float g_x2  [NTOK*DDIM];
static __device__ float g_att [NTOK*DDIM];

static __device__ __nv_bfloat16 g_wh[WTOTAL];        // weight hi
static __device__ __nv_bfloat16 g_wl[WTOTAL];        // weight lo
static __device__ __nv_bfloat16 g_qkvh[NTOK*D3];     // qkv hi
static __device__ __nv_bfloat16 g_qkvl[NTOK*D3];     // qkv lo
static __device__ __nv_bfloat16 g_p1h[NTOK*DDIM];
static __device__ __nv_bfloat16 g_p1l[NTOK*DDIM];
static __device__ __nv_bfloat16 g_p2h[NTOK*MDIM];
static __device__ __nv_bfloat16 g_p2l[NTOK*MDIM];

// ---------------------------------------------------------------------------
// Helpers
// ---------------------------------------------------------------------------
__device__ __forceinline__ void cp16(uint32_t d, const void* s) {
    asm volatile("cp.async.cg.shared.global [%0], [%1], 16;\n" :: "r"(d), "l"(s));
}
__device__ __forceinline__ void cp_commit() {
    asm volatile("cp.async.commit_group;\n" ::: "memory");
}
__device__ __forceinline__ void cp_wait2() {
    asm volatile("cp.async.wait_group 2;\n" ::: "memory");
}
__device__ __forceinline__ void cp_wait1() {
    asm volatile("cp.async.wait_group 1;\n" ::: "memory");
}
__device__ __forceinline__ void cp_wait0() {
    asm volatile("cp.async.wait_group 0;\n" ::: "memory");
}
__device__ __forceinline__ void ldsm4(uint32_t* r, uint32_t a) {
    asm volatile("ldmatrix.sync.aligned.m8n8.x4.shared.b16 {%0,%1,%2,%3}, [%4];"
        : "=r"(r[0]), "=r"(r[1]), "=r"(r[2]), "=r"(r[3]) : "r"(a));
}
__device__ __forceinline__ void ldsm4t(uint32_t* r, uint32_t a) {
    asm volatile("ldmatrix.sync.aligned.m8n8.x4.trans.shared.b16 {%0,%1,%2,%3}, [%4];"
        : "=r"(r[0]), "=r"(r[1]), "=r"(r[2]), "=r"(r[3]) : "r"(a));
}
__device__ __forceinline__ void mma16816(float* c, const uint32_t* a,
                                         uint32_t b0, uint32_t b1) {
    asm volatile(
        "mma.sync.aligned.m16n8k16.row.col.f32.bf16.bf16.f32 "
        "{%0,%1,%2,%3},{%4,%5,%6,%7},{%8,%9},{%0,%1,%2,%3};"
        : "+f"(c[0]), "+f"(c[1]), "+f"(c[2]), "+f"(c[3])
        : "r"(a[0]), "r"(a[1]), "r"(a[2]), "r"(a[3]), "r"(b0), "r"(b1));
}
__device__ __forceinline__ uint32_t pack2(__nv_bfloat16 a, __nv_bfloat16 b) {
    __nv_bfloat162 t = __halves2bfloat162(a, b);
    return *reinterpret_cast<uint32_t*>(&t);
}
__device__ __forceinline__ void split1(float v, __nv_bfloat16& h, __nv_bfloat16& l) {
    h = __float2bfloat16(v);
    l = __float2bfloat16(v - __bfloat162float(h));
}
__device__ __forceinline__ float bf2f(__nv_bfloat16 v) { return __bfloat162float(v); }

// ---------------------------------------------------------------------------
// Merged fp32 -> (hi,lo) bf16 split for all 6 weight tensors + x_in.
// One launch; block -> segment via cumulative block counts (4096 elems/block).
// ---------------------------------------------------------------------------
#define SPLIT_TOTAL_BLOCKS 16896

__global__ __launch_bounds__(256)
void split_all_kernel(const float* __restrict__ w_in1, const float* __restrict__ w_out1,
                      const float* __restrict__ w_in2, const float* __restrict__ w_out2,
                      const float* __restrict__ fw1,  const float* __restrict__ fw2,
                      const float* __restrict__ x,
                      __nv_bfloat16* __restrict__ WH, __nv_bfloat16* __restrict__ WL,
                      __nv_bfloat16* __restrict__ P1H, __nv_bfloat16* __restrict__ P1L)
{
    // segment boundaries in 4096-element blocks
    const int bid = blockIdx.x;
    const float* src;
    __nv_bfloat16 *dh, *dl;
    int rb;  // block index within segment
    if (bid < 3072)       { src = w_in1;  dh = WH + W_IN1_OFF;  dl = WL + W_IN1_OFF;  rb = bid; }
    else if (bid < 4096)  { src = w_out1; dh = WH + W_OUT1_OFF; dl = WL + W_OUT1_OFF; rb = bid - 3072; }
    else if (bid < 7168)  { src = w_in2;  dh = WH + W_IN2_OFF;  dl = WL + W_IN2_OFF;  rb = bid - 4096; }
    else if (bid < 8192)  { src = w_out2; dh = WH + W_OUT2_OFF; dl = WL + W_OUT2_OFF; rb = bid - 7168; }
    else if (bid < 12288) { src = fw1;    dh = WH + FW1_OFF;    dl = WL + FW1_OFF;    rb = bid - 8192; }
    else if (bid < 16384) { src = fw2;    dh = WH + FW2_OFF;    dl = WL + FW2_OFF;    rb = bid - 12288; }
    else                  { src = x;      dh = P1H;             dl = P1L;             rb = bid - 16384; }

    const size_t base = (size_t)rb * 4096 + threadIdx.x * 4;
    #pragma unroll
    for (int j = 0; j < 4; j++) {
        const size_t i = base + j * 1024;
        float4 v = *(const float4*)(src + i);
        __nv_bfloat16 h0,h1,h2,h3,l0,l1,l2,l3;
        split1(v.x,h0,l0); split1(v.y,h1,l1); split1(v.z,h2,l2); split1(v.w,h3,l3);
        uint2 uh; uh.x = pack2(h0,h1); uh.y = pack2(h2,h3);
        uint2 ul; ul.x = pack2(l0,l1); ul.y = pack2(l2,l3);
        *(uint2*)(dh + i) = uh;
        *(uint2*)(dl + i) = ul;
    }
}

// ---------------------------------------------------------------------------
// bf16x3 tensor-core GEMM: C[M,N] = A[M,K] @ Bw[N,K]^T + bias (+ epilogue)
// Templated on TM (CTA tile rows): 128 (4 warps, 64x64) or 64 (4 warps, 32x64).
// CTA tile TM x 128 x 32, 128 threads, cp.async 3-stage pipeline.
// EPI: 0=bias, 1=bias+GELU, 2=bias+residual.
// ---------------------------------------------------------------------------
template<int EPI, bool OSPLIT, bool OF32, int TM>
__global__ __launch_bounds__(128)
void gemm_bf3(const __nv_bfloat16* __restrict__ Ah, const __nv_bfloat16* __restrict__ Al,
              const __nv_bfloat16* __restrict__ Bh, const __nv_bfloat16* __restrict__ Bl,
              const float* __restrict__ bias, const float* __restrict__ Res,
              float* __restrict__ C, __nv_bfloat16* __restrict__ Chi,
              __nv_bfloat16* __restrict__ Clo, int M, int N, int K)
{
    constexpr int MF   = TM / 32;          // m-frags (16 rows) per warp
    constexpr int ASZ  = TM * 64;          // bytes per A matrix per stage
    constexpr int BREG = 2 * ASZ;          // B region byte offset
    constexpr int STG  = 2 * ASZ + 16384;  // stage bytes
    constexpr int KO_PER = TM / 32;        // A ko-chunks per thread (4 or 2)

    extern __shared__ __nv_bfloat16 smbuf[];
    const uint32_t smem_u32 = (uint32_t)__cvta_generic_to_shared(smbuf);

    const int tid = threadIdx.x;
    const int m0 = blockIdx.y * TM;
    const int n0 = blockIdx.x * 128;

    // ---- global->smem loader ----
    const int lrow = tid & (TM - 1);
    const int lrep = tid / TM;             // 0 for TM=128; 0..1 for TM=64
    const __nv_bfloat16* pAh = Ah + (size_t)(m0 + lrow) * K;
    const __nv_bfloat16* pAl = Al + (size_t)(m0 + lrow) * K;
    const __nv_bfloat16* pBh = Bh + (size_t)(n0 + tid) * K;
    const __nv_bfloat16* pBl = Bl + (size_t)(n0 + tid) * K;

    auto load_stage = [&](int kt, int s) {
        const uint32_t sb = smem_u32 + (uint32_t)s * STG;
        const size_t gk = (size_t)kt * 32;
        #pragma unroll
        for (int kk = 0; kk < KO_PER; kk++) {
            const int ko = lrep * KO_PER + kk;
            const uint32_t o = (uint32_t)ko * (TM * 16) + (uint32_t)lrow * 16;
            cp16(sb + o,       pAh + gk + ko * 8);
            cp16(sb + ASZ + o, pAl + gk + ko * 8);
        }
        #pragma unroll
        for (int ko = 0; ko < 4; ko++) {
            const uint32_t o = BREG + (uint32_t)ko * 2048 + (uint32_t)tid * 16;
            cp16(sb + o,        pBh + gk + ko * 8);
            cp16(sb + 8192 + o, pBl + gk + ko * 8);
        }
        cp_commit();
    };

    // ---- warp/frag mapping ----
    const int wid  = tid >> 5;
    const int lane = tid & 31;
    const int wm = (wid >> 1) * (TM / 2);
    const int wn = (wid & 1) * 64;
    const int a_row = lane & 15;
    const int a_ko  = lane >> 4;
    const int b_row = (lane & 7) + ((lane & 16) >> 1);
    const int b_ko  = (lane >> 3) & 1;

    const uint32_t aoff = (uint32_t)(a_ko * (TM * 16) + (wm + a_row) * 16);
    const uint32_t boff = (uint32_t)(BREG + b_ko * 2048 + (wn + b_row) * 16);

    float acc[MF][8][4];
    #pragma unroll
    for (int i = 0; i < MF; i++)
        #pragma unroll
        for (int j = 0; j < 8; j++)
            #pragma unroll
            for (int e = 0; e < 4; e++) acc[i][j][e] = 0.f;

    const int T = K >> 5;

    load_stage(0, 0);
    if (T > 1) load_stage(1, 1);

    for (int kt = 0; kt < T; kt++) {
        if (kt + 2 < T) { load_stage(kt + 2, (kt + 2) % 3); cp_wait2(); }
        else if (kt + 1 < T) cp_wait1();
        else cp_wait0();
        __syncthreads();

        const uint32_t sb = smem_u32 + (uint32_t)(kt % 3) * STG;
        #pragma unroll
        for (int ko0 = 0; ko0 < 4; ko0 += 2) {
            uint32_t a_h[MF][4], a_l[MF][4], b_h[16], b_l[16];
            #pragma unroll
            for (int mf = 0; mf < MF; mf++) {
                const uint32_t ad = sb + aoff + (uint32_t)ko0 * (TM * 16)
                                  + (uint32_t)mf * 256;
                ldsm4(a_h[mf], ad);
                ldsm4(a_l[mf], ad + ASZ);
            }
            #pragma unroll
            for (int nf2 = 0; nf2 < 4; nf2++) {
                const uint32_t bd = sb + boff + (uint32_t)ko0 * 2048
                                  + (uint32_t)nf2 * 256;
                ldsm4(&b_h[nf2*4], bd);
                ldsm4(&b_l[nf2*4], bd + 8192);
            }
            #pragma unroll
            for (int mf = 0; mf < MF; mf++)
                #pragma unroll
                for (int nf = 0; nf < 8; nf++) {
                    mma16816(acc[mf][nf], a_h[mf], b_h[nf*2], b_h[nf*2+1]);
                    mma16816(acc[mf][nf], a_h[mf], b_l[nf*2], b_l[nf*2+1]);
                    mma16816(acc[mf][nf], a_l[mf], b_h[nf*2], b_h[nf*2+1]);
                }
        }
        __syncthreads();
    }

    // ---- epilogue ----
    const int er = lane >> 2;
    const int ec = (lane & 3) * 2;
    #pragma unroll
    for (int mf = 0; mf < MF; mf++) {
        #pragma unroll
        for (int nf = 0; nf < 8; nf++) {
            const int m = m0 + wm + mf*16 + er;
            const int n = n0 + wn + nf*8 + ec;
            const float2 bv = *(const float2*)(bias + n);
            #pragma unroll
            for (int half = 0; half < 2; half++) {
                const int mm = m + half*8;
                float t0 = acc[mf][nf][half*2+0] + bv.x;
                float t1 = acc[mf][nf][half*2+1] + bv.y;
                if (EPI == 1) {
                    t0 = 0.5f * t0 * (1.f + erff(t0 * 0.70710678118654752f));
                    t1 = 0.5f * t1 * (1.f + erff(t1 * 0.70710678118654752f));
                }
                if (EPI == 2) {
                    const float2 rv = *(const float2*)(Res + (size_t)mm * N + n);
                    t0 += rv.x; t1 += rv.y;
                }
                if (OF32) {
                    *(float2*)(C + (size_t)mm * N + n) = make_float2(t0, t1);
                }
                if (OSPLIT) {
                    __nv_bfloat16 h0,h1,l0,l1;
                    split1(t0,h0,l0); split1(t1,h1,l1);
                    *(uint32_t*)(Chi + (size_t)mm * N + n) = pack2(h0,h1);
                    *(uint32_t*)(Clo + (size_t)mm * N + n) = pack2(l0,l1);
                }
            }
        }
    }
}

#define GS128 (3*(2*128*64 + 16384))   // 98304
#define GS64  (3*(2*64*64  + 16384))   // 73728

// ---------------------------------------------------------------------------
// Tensor-core full attention (bf16x3 flash) — unchanged from round 7.
// ---------------------------------------------------------------------------
#define ATTN_TC_SMEM 65536

__global__ __launch_bounds__(128, 3)
void attn_tc_kernel(const __nv_bfloat16* __restrict__ qkvh,
                    const __nv_bfloat16* __restrict__ qkvl,
                    __nv_bfloat16* __restrict__ oh,
                    __nv_bfloat16* __restrict__ ol)
{
    extern __shared__ char smc[];
    const uint32_t sb = (uint32_t)__cvta_generic_to_shared(smc);

    const int bh = blockIdx.x;
    const int b  = bh >> 4;
    const int h  = bh & 15;
    const int qt = blockIdx.y;
    const int tid  = threadIdx.x;
    const int wid  = tid >> 5;
    const int lane = tid & 31;

    const int r    = tid >> 1;
    const int koh  = (tid & 1) * 4;

    {
        const size_t qrow = (size_t)(b*SLEN + qt*64 + r) * D3 + h*HD;
        #pragma unroll
        for (int it = 0; it < 4; it++) {
            const int ko = koh + it;
            const uint32_t dst = sb + (uint32_t)(((ko*64 + r)*8) * 2);
            cp16(dst,        qkvh + qrow + ko*8);
            cp16(dst + 8192, qkvl + qrow + ko*8);
        }
        cp_commit();
    }

    const int a_row = lane & 15;
    const int a_ko  = lane >> 4;
    const int b_row = (lane & 7) + ((lane & 16) >> 1);
    const int b_ko  = (lane >> 3) & 1;
    const int v_key = lane & 15;
    const int v_ko  = lane >> 4;

    uint32_t qa_h[4][4], qa_l[4][4];

    cp_wait0();
    __syncthreads();
    #pragma unroll
    for (int ks = 0; ks < 4; ks++) {
        const uint32_t ad = sb +
            (uint32_t)((((ks*2 + a_ko)*64 + wid*16 + a_row)*8) * 2);
        ldsm4(qa_h[ks], ad);
        ldsm4(qa_l[ks], ad + 8192);
    }
    __syncthreads();

    auto load_kv = [&](int kt, int s) {
        const uint32_t stg = sb + (uint32_t)s * 32768;
        const size_t krow = (size_t)(b*SLEN + kt*64 + r) * D3 + DDIM + h*HD;
        const size_t vrow = krow + DDIM;
        #pragma unroll
        for (int it = 0; it < 4; it++) {
            const int ko = koh + it;
            const uint32_t off = (uint32_t)(((ko*64 + r)*8) * 2);
            cp16(stg + off,          qkvh + krow + ko*8);
            cp16(stg + 8192  + off,  qkvl + krow + ko*8);
            cp16(stg + 16384 + off,  qkvh + vrow + ko*8);
            cp16(stg + 24576 + off,  qkvl + vrow + ko*8);
        }
    };

    load_kv(0, 0);
    cp_commit();

    float m0 = -1e30f, m1 = -1e30f, l0 = 0.f, l1 = 0.f;
    float oacc[8][4];
    #pragma unroll
    for (int nf = 0; nf < 8; nf++)
        #pragma unroll
        for (int e = 0; e < 4; e++) oacc[nf][e] = 0.f;

    for (int kt = 0; kt < 16; kt++) {
        const int s = kt & 1;
        if (kt + 1 < 16) {
            load_kv(kt + 1, s ^ 1);
            cp_commit();
            cp_wait1();
        } else {
            cp_wait0();
        }
        __syncthreads();

        const uint32_t stg = sb + (uint32_t)s * 32768;

        float sc[8][4];
        #pragma unroll
        for (int nf = 0; nf < 8; nf++)
            #pragma unroll
            for (int e = 0; e < 4; e++) sc[nf][e] = 0.f;

        #pragma unroll
        for (int ks = 0; ks < 4; ks++) {
            #pragma unroll
            for (int np = 0; np < 4; np++) {
                uint32_t kb[4], kl[4];
                const uint32_t kd = stg +
                    (uint32_t)((((ks*2 + b_ko)*64 + np*16 + b_row)*8) * 2);
                ldsm4(kb, kd);
                ldsm4(kl, kd + 8192);
                mma16816(sc[2*np],   qa_h[ks], kb[0], kb[1]);
                mma16816(sc[2*np],   qa_h[ks], kl[0], kl[1]);
                mma16816(sc[2*np],   qa_l[ks], kb[0], kb[1]);
                mma16816(sc[2*np+1], qa_h[ks], kb[2], kb[3]);
                mma16816(sc[2*np+1], qa_h[ks], kl[2], kl[3]);
                mma16816(sc[2*np+1], qa_l[ks], kb[2], kb[3]);
            }
        }

        #pragma unroll
        for (int nf = 0; nf < 8; nf++)
            #pragma unroll
            for (int e = 0; e < 4; e++) sc[nf][e] *= 0.125f;

        float mx0 = m0, mx1 = m1;
        #pragma unroll
        for (int nf = 0; nf < 8; nf++) {
            mx0 = fmaxf(mx0, fmaxf(sc[nf][0], sc[nf][1]));
            mx1 = fmaxf(mx1, fmaxf(sc[nf][2], sc[nf][3]));
        }
        mx0 = fmaxf(mx0, __shfl_xor_sync(0xffffffffu, mx0, 1));
        mx0 = fmaxf(mx0, __shfl_xor_sync(0xffffffffu, mx0, 2));
        mx1 = fmaxf(mx1, __shfl_xor_sync(0xffffffffu, mx1, 1));
        mx1 = fmaxf(mx1, __shfl_xor_sync(0xffffffffu, mx1, 2));

        const float al0 = __expf(m0 - mx0);
        const float al1 = __expf(m1 - mx1);
        m0 = mx0; m1 = mx1;

        float s0 = 0.f, s1 = 0.f;
        uint32_t pah[4][4], pal[4][4];
        #pragma unroll
        for (int nf = 0; nf < 8; nf++) {
            const float p0 = __expf(sc[nf][0] - m0);
            const float p1 = __expf(sc[nf][1] - m0);
            const float p2 = __expf(sc[nf][2] - m1);
            const float p3 = __expf(sc[nf][3] - m1);
            s0 += p0 + p1;
            s1 += p2 + p3;
            __nv_bfloat16 h0,h1,h2,h3,lo0,lo1,lo2,lo3;
            split1(p0,h0,lo0); split1(p1,h1,lo1);
            split1(p2,h2,lo2); split1(p3,h3,lo3);
            const int ks = nf >> 1;
            const int hv = (nf & 1) * 2;
            pah[ks][hv+0] = pack2(h0, h1);
            pah[ks][hv+1] = pack2(h2, h3);
            pal[ks][hv+0] = pack2(lo0, lo1);
            pal[ks][hv+1] = pack2(lo2, lo3);
        }
        s0 += __shfl_xor_sync(0xffffffffu, s0, 1);
        s0 += __shfl_xor_sync(0xffffffffu, s0, 2);
        s1 += __shfl_xor_sync(0xffffffffu, s1, 1);
        s1 += __shfl_xor_sync(0xffffffffu, s1, 2);
        l0 = l0 * al0 + s0;
        l1 = l1 * al1 + s1;

        #pragma unroll
        for (int nf = 0; nf < 8; nf++) {
            oacc[nf][0] *= al0; oacc[nf][1] *= al0;
            oacc[nf][2] *= al1; oacc[nf][3] *= al1;
        }

        #pragma unroll
        for (int ks = 0; ks < 4; ks++) {
            #pragma unroll
            for (int np = 0; np < 4; np++) {
                uint32_t vb[4], vl[4];
                const uint32_t vd = stg + 16384 +
                    (uint32_t)((((np*2 + v_ko)*64 + ks*16 + v_key)*8) * 2);
                ldsm4t(vb, vd);
                ldsm4t(vl, vd + 8192);
                mma16816(oacc[2*np],   pah[ks], vb[0], vb[1]);
                mma16816(oacc[2*np],   pah[ks], vl[0], vl[1]);
                mma16816(oacc[2*np],   pal[ks], vb[0], vb[1]);
                mma16816(oacc[2*np+1], pah[ks], vb[2], vb[3]);
                mma16816(oacc[2*np+1], pah[ks], vl[2], vl[3]);
                mma16816(oacc[2*np+1], pal[ks], vb[2], vb[3]);
            }
        }
        __syncthreads();
    }

    const float inv0 = 1.f / l0;
    const float inv1 = 1.f / l1;
    const int er  = lane >> 2;
    const int ec  = (lane & 3) * 2;
    const int tok0 = b*SLEN + qt*64 + wid*16 + er;
    const int tok1 = tok0 + 8;
    #pragma unroll
    for (int nf = 0; nf < 8; nf++) {
        const int col = h*HD + nf*8 + ec;
        const float o0 = oacc[nf][0] * inv0;
        const float o1 = oacc[nf][1] * inv0;
        const float o2 = oacc[nf][2] * inv1;
        const float o3 = oacc[nf][3] * inv1;
        __nv_bfloat16 h0,h1,h2,h3,lo0,lo1,lo2,lo3;
        split1(o0,h0,lo0); split1(o1,h1,lo1);
        split1(o2,h2,lo2); split1(o3,h3,lo3);
        *(uint32_t*)(oh + (size_t)tok0 * DDIM + col) = pack2(h0, h1);
        *(uint32_t*)(ol + (size_t)tok0 * DDIM + col) = pack2(lo0, lo1);
        *(uint32_t*)(oh + (size_t)tok1 * DDIM + col) = pack2(h2, h3);
        *(uint32_t*)(ol + (size_t)tok1 * DDIM + col) = pack2(lo2, lo3);
    }
}

// ---------------------------------------------------------------------------
// Banded attention — unchanged.
// ---------------------------------------------------------------------------
__global__ __launch_bounds__(256)
void attn_band_kernel(const __nv_bfloat16* __restrict__ qkvh,
                      const __nv_bfloat16* __restrict__ qkvl,
                      __nv_bfloat16* __restrict__ oh,
                      __nv_bfloat16* __restrict__ ol)
{
    const int gw   = (blockIdx.x * blockDim.x + threadIdx.x) >> 5;
    const int lane = threadIdx.x & 31;
    const int i = gw & (SLEN-1);
    const int h = (gw >> 10) & (HNUM-1);
    const int b = gw >> 14;

    const size_t qbase = (size_t)(b*SLEN + i) * D3 + h*HD;
    const float q0 = bf2f(qkvh[qbase + lane])      + bf2f(qkvl[qbase + lane]);
    const float q1 = bf2f(qkvh[qbase + 32 + lane]) + bf2f(qkvl[qbase + 32 + lane]);

    float sc[5];
    int   jc[5];
    #pragma unroll
    for (int jj = 0; jj < 5; jj++) {
        int j = i - 2 + jj;
        bool valid = (j >= 0) && (j < SLEN);
        jc[jj] = valid ? j : i;
        const size_t kb = (size_t)(b*SLEN + jc[jj]) * D3 + DDIM + h*HD;
        const float k0 = bf2f(qkvh[kb + lane])      + bf2f(qkvl[kb + lane]);
        const float k1 = bf2f(qkvh[kb + 32 + lane]) + bf2f(qkvl[kb + 32 + lane]);
        float p = q0 * k0 + q1 * k1;
        #pragma unroll
        for (int off = 16; off; off >>= 1) p += __shfl_xor_sync(0xffffffffu, p, off);
        sc[jj] = valid ? p * 0.125f : -1e30f;
    }
    float mx = sc[0];
    #pragma unroll
    for (int jj = 1; jj < 5; jj++) mx = fmaxf(mx, sc[jj]);
    float w[5], sum = 0.f;
    #pragma unroll
    for (int jj = 0; jj < 5; jj++) { w[jj] = __expf(sc[jj] - mx); sum += w[jj]; }
    const float inv = 1.f / sum;

    float o0 = 0.f, o1 = 0.f;
    #pragma unroll
    for (int jj = 0; jj < 5; jj++) {
        const size_t vb = (size_t)(b*SLEN + jc[jj]) * D3 + 2*DDIM + h*HD;
        const float v0 = bf2f(qkvh[vb + lane])      + bf2f(qkvl[vb + lane]);
        const float v1 = bf2f(qkvh[vb + 32 + lane]) + bf2f(qkvl[vb + 32 + lane]);
        o0 = fmaf(w[jj], v0, o0);
        o1 = fmaf(w[jj], v1, o1);
    }
    o0 *= inv; o1 *= inv;

    const size_t ob = (size_t)(b*SLEN + i) * DDIM + h*HD;
    __nv_bfloat16 hh, ll;
    split1(o0, hh, ll);
    oh[ob + lane] = hh;  ol[ob + lane] = ll;
    split1(o1, hh, ll);
    oh[ob + 32 + lane] = hh;  ol[ob + 32 + lane] = ll;
}

// ---------------------------------------------------------------------------
// LayerNorm — unchanged.
// ---------------------------------------------------------------------------
__global__ __launch_bounds__(256)
void ln_kernel(const float* __restrict__ a, const float* __restrict__ r,
               const float* __restrict__ g, const float* __restrict__ bt,
               float* __restrict__ out,
               __nv_bfloat16* __restrict__ ohh, __nv_bfloat16* __restrict__ oll)
{
    __shared__ float red[2][8];
    __shared__ float s_mean, s_rstd;
    const int n = blockIdx.x;
    const int tid = threadIdx.x;
    const size_t base = (size_t)n * DDIM + tid * 4;

    float4 va = *(const float4*)(a + base);
    if (r) {
        float4 vr = *(const float4*)(r + base);
        va.x += vr.x; va.y += vr.y; va.z += vr.z; va.w += vr.w;
    }
    float s  = va.x + va.y + va.z + va.w;
    float sq = va.x*va.x + va.y*va.y + va.z*va.z + va.w*va.w;

    #pragma unroll
    for (int off = 16; off; off >>= 1) {
        s  += __shfl_xor_sync(0xffffffffu, s,  off);
        sq += __shfl_xor_sync(0xffffffffu, sq, off);
    }
    const int wid = tid >> 5;
    if ((tid & 31) == 0) { red[0][wid] = s; red[1][wid] = sq; }
    __syncthreads();
    if (tid < 32) {
        float ts  = (tid < 8) ? red[0][tid] : 0.f;
        float tsq = (tid < 8) ? red[1][tid] : 0.f;
        #pragma unroll
        for (int off = 4; off; off >>= 1) {
            ts  += __shfl_xor_sync(0xffffffffu, ts,  off);
            tsq += __shfl_xor_sync(0xffffffffu, tsq, off);
        }
        if (tid == 0) {
            float mean = ts * (1.f / DDIM);
            float var  = tsq * (1.f / DDIM) - mean * mean;
            s_mean = mean;
            s_rstd = rsqrtf(var + EPS);
        }
    }
    __syncthreads();
    const float mean = s_mean, rstd = s_rstd;
    float4 gg = *(const float4*)(g + tid*4);
    float4 bb = *(const float4*)(bt + tid*4);
    float4 o;
    o.x = (va.x - mean) * rstd * gg.x + bb.x;
    o.y = (va.y - mean) * rstd * gg.y + bb.y;
    o.z = (va.z - mean) * rstd * gg.z + bb.z;
    o.w = (va.w - mean) * rstd * gg.w + bb.w;
    *(float4*)(out + base) = o;
    if (ohh) {
        __nv_bfloat16 h0,h1,h2,h3,l0,l1,l2,l3;
        split1(o.x,h0,l0); split1(o.y,h1,l1); split1(o.z,h2,l2); split1(o.w,h3,l3);
        uint2 uh; uh.x = pack2(h0,h1); uh.y = pack2(h2,h3);
        uint2 ul; ul.x = pack2(l0,l1); ul.y = pack2(l2,l3);
        *(uint2*)(ohh + base) = uh;
        *(uint2*)(oll + base) = ul;
    }
}

// ---------------------------------------------------------------------------
// Orchestration
// ---------------------------------------------------------------------------
extern "C" void kernel_launch(void* const* d_in, const int* in_sizes, int n_in,
                              void* d_out, int out_size)
{
    const float* x_in   = (const float*)d_in[0];
    const float* w_in1  = (const float*)d_in[1];
    const float* b_in1  = (const float*)d_in[2];
    const float* w_out1 = (const float*)d_in[3];
    const float* b_out1 = (const float*)d_in[4];
    const float* ln1_g  = (const float*)d_in[5];
    const float* ln1_b  = (const float*)d_in[6];
    const float* w_in2  = (const float*)d_in[7];
    const float* b_in2  = (const float*)d_in[8];
    const float* w_out2 = (const float*)d_in[9];
    const float* b_out2 = (const float*)d_in[10];
    const float* ln2_g  = (const float*)d_in[11];
    const float* ln2_b  = (const float*)d_in[12];
    const float* ffn_w1 = (const float*)d_in[13];
    const float* ffn_b1 = (const float*)d_in[14];
    const float* ffn_w2 = (const float*)d_in[15];
    const float* ffn_b2 = (const float*)d_in[16];
    const float* lnf_g  = (const float*)d_in[17];
    const float* lnf_b  = (const float*)d_in[18];

    float *PROJ, *X, *X2, *ATT;
    __nv_bfloat16 *WH, *WL, *QKVH, *QKVL, *P1H, *P1L, *P2H, *P2L;
    cudaGetSymbolAddress((void**)&PROJ, g_proj);
    cudaGetSymbolAddress((void**)&X,    g_x);
    cudaGetSymbolAddress((void**)&X2,   g_x2);
    cudaGetSymbolAddress((void**)&ATT,  g_att);
    cudaGetSymbolAddress((void**)&WH,   g_wh);
    cudaGetSymbolAddress((void**)&WL,   g_wl);
    cudaGetSymbolAddress((void**)&QKVH, g_qkvh);
    cudaGetSymbolAddress((void**)&QKVL, g_qkvl);
    cudaGetSymbolAddress((void**)&P1H,  g_p1h);
    cudaGetSymbolAddress((void**)&P1L,  g_p1l);
    cudaGetSymbolAddress((void**)&P2H,  g_p2h);
    cudaGetSymbolAddress((void**)&P2L,  g_p2l);

    cudaFuncSetAttribute(attn_tc_kernel,
                         cudaFuncAttributeMaxDynamicSharedMemorySize, ATTN_TC_SMEM);
    cudaFuncSetAttribute(gemm_bf3<0,true,false,128>,
                         cudaFuncAttributeMaxDynamicSharedMemorySize, GS128);
    cudaFuncSetAttribute(gemm_bf3<1,true,false,128>,
                         cudaFuncAttributeMaxDynamicSharedMemorySize, GS128);
    cudaFuncSetAttribute(gemm_bf3<0,false,true,64>,
                         cudaFuncAttributeMaxDynamicSharedMemorySize, GS64);
    cudaFuncSetAttribute(gemm_bf3<2,true,true,64>,
                         cudaFuncAttributeMaxDynamicSharedMemorySize, GS64);

    const dim3 blk(256);
    const dim3 gblk(128);
    const dim3 g_qkvp(D3/128,  NTOK/128);    // (24,16)
    const dim3 g_outp(DDIM/128, NTOK/64);    // (8,32)  TM=64
    const dim3 g_ffn1(MDIM/128, NTOK/128);   // (32,16)
    const dim3 g_ffn2(DDIM/128, NTOK/64);    // (8,32)  TM=64
    const dim3 g_attn(BNUM*HNUM, SLEN/64);   // (32,16)
    const int  g_band = (BNUM*HNUM*SLEN*32) / 256;
    const int  g_ln   = NTOK;

    // ---- single merged split launch: all 6 weights + layer-0 input ----
    split_all_kernel<<<SPLIT_TOTAL_BLOCKS, blk>>>(
        w_in1, w_out1, w_in2, w_out2, ffn_w1, ffn_w2, x_in,
        WH, WL, P1H, P1L);

    const float* xcur = x_in;
    for (int l = 0; l < LNUM; l++) {
        const size_t oW3 = (size_t)l * D3 * DDIM;
        const size_t oW1 = (size_t)l * DDIM * DDIM;
        const size_t oWm = (size_t)l * MDIM * DDIM;

        // ---- intra-frame full MHA ----
        gemm_bf3<0,true,false,128><<<g_qkvp, gblk, GS128>>>(
            P1H, P1L, WH+W_IN1_OFF+oW3, WL+W_IN1_OFF+oW3,
            b_in1 + (size_t)l*D3, nullptr, nullptr, QKVH, QKVL, NTOK, D3, DDIM);
        attn_tc_kernel<<<g_attn, 128, ATTN_TC_SMEM>>>(QKVH, QKVL, P1H, P1L);
        gemm_bf3<0,false,true,64><<<g_outp, gblk, GS64>>>(
            P1H, P1L, WH+W_OUT1_OFF+oW1, WL+W_OUT1_OFF+oW1,
            b_out1 + (size_t)l*DDIM, nullptr, PROJ, nullptr, nullptr, NTOK, DDIM, DDIM);
        ln_kernel<<<g_ln, blk>>>(PROJ, xcur, ln1_g + (size_t)l*DDIM,
                                 ln1_b + (size_t)l*DDIM, X2, P1H, P1L);

        // ---- inter-frame banded MHA ----
        gemm_bf3<0,true,false,128><<<g_qkvp, gblk, GS128>>>(
            P1H, P1L, WH+W_IN2_OFF+oW3, WL+W_IN2_OFF+oW3,
            b_in2 + (size_t)l*D3, nullptr, nullptr, QKVH, QKVL, NTOK, D3, DDIM);
        attn_band_kernel<<<g_band, blk>>>(QKVH, QKVL, P1H, P1L);
        gemm_bf3<0,false,true,64><<<g_outp, gblk, GS64>>>(
            P1H, P1L, WH+W_OUT2_OFF+oW1, WL+W_OUT2_OFF+oW1,
            b_out2 + (size_t)l*DDIM, nullptr, PROJ, nullptr, nullptr, NTOK, DDIM, DDIM);
        ln_kernel<<<g_ln, blk>>>(PROJ, X2, ln2_g + (size_t)l*DDIM,
                                 ln2_b + (size_t)l*DDIM, ATT, P1H, P1L);

        // ---- FFN ----
        gemm_bf3<1,true,false,128><<<g_ffn1, gblk, GS128>>>(
            P1H, P1L, WH+FW1_OFF+oWm, WL+FW1_OFF+oWm,
            ffn_b1 + (size_t)l*MDIM, nullptr, nullptr, P2H, P2L, NTOK, MDIM, DDIM);
        gemm_bf3<2,true,true,64><<<g_ffn2, gblk, GS64>>>(
            P2H, P2L, WH+FW2_OFF+oWm, WL+FW2_OFF+oWm,
            ffn_b2 + (size_t)l*DDIM, ATT, X, P1H, P1L, NTOK, DDIM, MDIM);
        xcur = X;
    }

    ln_kernel<<<g_ln, blk>>>(xcur, nullptr, lnf_g, lnf_b, (float*)d_out,
                             nullptr, nullptr);
}